// round 1
// baseline (speedup 1.0000x reference)
#include <cuda_runtime.h>

// Signature (depth 5) of piecewise-linear paths.
// B=256 batch, d=10 channels, L=128 points -> 127 segments.
// Output per batch row: [S1(10) | S2(100) | S3(1000) | S4(10000) | S5(100000)] = 111110 floats.
//
// Chen relation with rank-1 segment signatures T_k = delta^{(x)k}/k! collapses to:
//   S5 += X4 (x) delta,  X4[abcd] = S4[abcd] + d_d * P3[abc]
//   S4 += Y3 (x) delta,  Y3[abc]  = S3 + d_c*(S2/2 + d_b*(S1/6 + d_a/24))
//   P3[abc] = S3/2 + d_c*(S2/6 + d_b*(S1/24 + d_a/120))
//   S3 += Z2 (x) delta,  Z2[ab]   = S2 + d_b*(S1/2 + d_a/6)
//   S2 += W1 (x) delta,  W1[a]    = S1 + d_a/2
//   S1 += delta
// Starting from S=0, one uniform loop over all 127 increments reproduces the init term.

#define NB 256
#define DCH 10
#define LEN 128
#define NSEG 127
#define CTAS_PER_B 5
#define THREADS 1024
#define ROW 111110

// packed f32x2 helpers (Blackwell native 2x-rate fp32 path)
__device__ __forceinline__ unsigned long long pk(float lo, float hi) {
    unsigned long long r;
    asm("mov.b64 %0, {%1, %2};" : "=l"(r) : "f"(lo), "f"(hi));
    return r;
}
__device__ __forceinline__ void upk(unsigned long long v, float& lo, float& hi) {
    asm("mov.b64 {%0, %1}, %2;" : "=f"(lo), "=f"(hi) : "l"(v));
}
__device__ __forceinline__ unsigned long long ffma2(unsigned long long a,
                                                    unsigned long long b,
                                                    unsigned long long c) {
    unsigned long long d;
    asm("fma.rn.f32x2 %0, %1, %2, %3;" : "=l"(d) : "l"(a), "l"(b), "l"(c));
    return d;
}

__global__ __launch_bounds__(THREADS, 1)
void sig_kernel(const float* __restrict__ path, float* __restrict__ out) {
    __shared__ __align__(16) float sdelta[NSEG * DCH];  // [t][c], row stride 10 floats (8B-aligned rows)
    __shared__ float S1sh[2];     // a_local in {0,1}, global a = 2j + a_local
    __shared__ float S2sh[20];    // [a_local*10 + b]
    __shared__ float S3sh[200];   // [a_local*100 + b*10 + c]
    __shared__ __align__(16) float2 Hsh[200];  // (P3, Y3) per local abc

    const int tid = threadIdx.x;
    const int b   = blockIdx.x / CTAS_PER_B;
    const int j   = blockIdx.x % CTAS_PER_B;   // this CTA owns channels a in {2j, 2j+1}

    // ---- load segment increments (coalesced over t) ----
    const float* pb = path + b * (DCH * LEN);
    for (int idx = tid; idx < NSEG * DCH; idx += THREADS) {
        int c = idx / NSEG, t = idx % NSEG;
        sdelta[t * DCH + c] = pb[c * LEN + t + 1] - pb[c * LEN + t];
    }
    if (tid < 2)   S1sh[tid] = 0.f;
    if (tid < 20)  S2sh[tid] = 0.f;
    if (tid < 200) S3sh[tid] = 0.f;

    // ---- thread ownership ----
    const bool is_main = tid < 1000;
    const int abc_l = tid / 5;   // local abc, 0..199
    const int dd    = tid % 5;   // owns d = dd and d = dd+5
    // helper decode (tid < 200): local abc = tid
    const int hc  = tid % 10;           // c
    const int hab = tid / 10;           // a_local*10 + b
    const int hb  = hab % 10;           // b
    const int ha  = hab / 10;           // a_local

    unsigned long long s5[2][5];        // [d-group][e-pair], e pairs (0,1)..(8,9)
    unsigned long long s4p = 0ull;      // (S4[abc,dd], S4[abc,dd+5])
#pragma unroll
    for (int g = 0; g < 2; ++g)
#pragma unroll
        for (int p = 0; p < 5; ++p) s5[g][p] = 0ull;

    for (int t = 0; t < NSEG; ++t) {
        __syncthreads();  // prev-iter S1/S2 writes + (iter 0) init/delta visible
        const float* dl = &sdelta[t * DCH];
        float s2new = 0.f, s1new = 0.f;

        if (tid < 200) {
            float s3 = S3sh[tid], s2 = S2sh[hab], s1 = S1sh[ha];
            float da = dl[2 * j + ha], db = dl[hb], dc = dl[hc];
            float P1 = fmaf(da, 1.f / 120.f, s1 * (1.f / 24.f));
            float P2 = fmaf(db, P1, s2 * (1.f / 6.f));
            float P3 = fmaf(dc, P2, s3 * 0.5f);
            float Q1 = fmaf(da, 1.f / 24.f, s1 * (1.f / 6.f));
            float Q2 = fmaf(db, Q1, s2 * 0.5f);
            float Y3 = fmaf(dc, Q2, s3);
            float Z1 = fmaf(da, 1.f / 6.f, s1 * 0.5f);
            float Z2 = fmaf(db, Z1, s2);
            Hsh[tid] = make_float2(P3, Y3);
            S3sh[tid] = fmaf(dc, Z2, s3);  // only this thread touches this entry
        }
        if (tid < 20) {
            int a2 = tid / 10, b2 = tid % 10;
            float W1 = fmaf(dl[2 * j + a2], 0.5f, S1sh[a2]);
            s2new = fmaf(dl[b2], W1, S2sh[tid]);
        }
        if (tid < 2) s1new = S1sh[tid] + dl[2 * j + tid];

        __syncthreads();  // H ready; all old S1/S2 reads done
        if (tid < 20) S2sh[tid] = s2new;
        if (tid < 2)  S1sh[tid] = s1new;

        if (is_main) {
            float2 Hv = Hsh[abc_l];                  // (P3, Y3)
            float d0 = dl[dd], d1 = dl[dd + 5];
            unsigned long long ddp = pk(d0, d1);
            unsigned long long Hxx = pk(Hv.x, Hv.x);
            unsigned long long Hyy = pk(Hv.y, Hv.y);
            unsigned long long X4p = ffma2(ddp, Hxx, s4p);  // (X4_d0, X4_d1)
            s4p = ffma2(ddp, Hyy, s4p);                      // S4 update
            float x0, x1;
            upk(X4p, x0, x1);
            unsigned long long X00 = pk(x0, x0), X11 = pk(x1, x1);
            const float2* dl2 = (const float2*)dl;           // rows are 8B-aligned
#pragma unroll
            for (int p = 0; p < 5; ++p) {
                float2 dv = dl2[p];
                unsigned long long dp = pk(dv.x, dv.y);
                s5[0][p] = ffma2(X00, dp, s5[0][p]);
                s5[1][p] = ffma2(X11, dp, s5[1][p]);
            }
        }
    }

    __syncthreads();

    // ---- epilogue: write this CTA's slice of the output row ----
    float* orow = out + (size_t)b * ROW;
    if (tid < 2)   orow[2 * j + tid] = S1sh[tid];
    if (tid < 20)  orow[10 + 20 * j + tid] = S2sh[tid];
    if (tid < 200) orow[110 + 200 * j + tid] = S3sh[tid];
    if (is_main) {
        int abc   = 200 * j + abc_l;       // global abc
        int abcd0 = abc * 10 + dd;
        int abcd1 = abc * 10 + dd + 5;
        float s40, s41;
        upk(s4p, s40, s41);
        orow[1110 + abcd0] = s40;
        orow[1110 + abcd1] = s41;
        float2* o5 = (float2*)(orow + 11110);  // 8B-aligned: 11110*4 % 8 == 0, row even
#pragma unroll
        for (int p = 0; p < 5; ++p) {
            float lo, hi;
            upk(s5[0][p], lo, hi);
            o5[abcd0 * 5 + p] = make_float2(lo, hi);
            upk(s5[1][p], lo, hi);
            o5[abcd1 * 5 + p] = make_float2(lo, hi);
        }
    }
}

extern "C" void kernel_launch(void* const* d_in, const int* in_sizes, int n_in,
                              void* d_out, int out_size) {
    const float* path = (const float*)d_in[0];  // (256, 10, 128) fp32
    // d_in[1] = depth (constant 5), ignored
    float* out = (float*)d_out;                 // (256, 111110) fp32
    sig_kernel<<<NB * CTAS_PER_B, THREADS>>>(path, out);
}

// round 2
// speedup vs baseline: 1.2493x; 1.2493x over previous
#include <cuda_runtime.h>

// Depth-5 path signature, B=256, d=10, L=128 (127 segments).
// Output row: [S1(10) | S2(100) | S3(1000) | S4(10000) | S5(100000)] = 111110 floats.
//
// Chen recurrence with rank-1 segment tensors collapses to (per segment, increment δ):
//   P3[abc] = S3/2 + δc*(S2/6 + δb*(S1/24 + δa/120))
//   Y3[abc] = S3   + δc*(S2/2 + δb*(S1/6  + δa/24))
//   X4[abcd] = S4[abcd] + δd*P3[abc];  S4 += Y3 ⊗ δ;  S5 += X4 ⊗ δ
//   S3 += δc*(S2 + δb*(S1/2 + δa/6));  S2 += δb*(S1 + δa/2);  S1 += δ
//
// CTA owns a ∈ {2j, 2j+1}. 1000 main threads: thread = (local abc, d-pair dd/dd+5),
// keeps S4 pair + 10 packed S5 accumulators in registers (fma.rn.f32x2 path).
// 200 helper threads keep S1/S2/S3 in registers (redundant copies -> no cross-thread
// state reads -> single barrier per segment, double-buffered H=(P3,Y3)).

#define NB 256
#define DCH 10
#define LEN 128
#define NSEG 127
#define CTAS_PER_B 5
#define THREADS 1024
#define ROW 111110
#define APAD 12   // padded row stride of sdA (48B -> 16B-aligned rows)

typedef unsigned long long ull;

__device__ __forceinline__ ull pk(float lo, float hi) {
    ull r;
    asm("mov.b64 %0, {%1, %2};" : "=l"(r) : "f"(lo), "f"(hi));
    return r;
}
__device__ __forceinline__ void upk(ull v, float& lo, float& hi) {
    asm("mov.b64 {%0, %1}, %2;" : "=f"(lo), "=f"(hi) : "l"(v));
}
__device__ __forceinline__ ull ffma2(ull a, ull b, ull c) {
    ull d;
    asm("fma.rn.f32x2 %0, %1, %2, %3;" : "=l"(d) : "l"(a), "l"(b), "l"(c));
    return d;
}

__global__ __launch_bounds__(THREADS, 1)
void sig_kernel(const float* __restrict__ path, float* __restrict__ out) {
    __shared__ __align__(16) float sdA[NSEG * APAD];   // [t][c], 48B rows for LDS.128
    __shared__ __align__(8)  float sdP[NSEG * DCH];    // [t][dd] = (δ_dd, δ_dd+5) pairs
    __shared__ __align__(16) float2 Hsh[2][200];       // double-buffered (P3, Y3)

    const int tid = threadIdx.x;
    const int b   = blockIdx.x / CTAS_PER_B;
    const int j   = blockIdx.x % CTAS_PER_B;           // a ∈ {2j, 2j+1}

    // ---- segment increments into both SMEM layouts ----
    const float* pb = path + b * (DCH * LEN);
    for (int idx = tid; idx < NSEG * DCH; idx += THREADS) {
        int c = idx / NSEG, t = idx % NSEG;
        float d = pb[c * LEN + t + 1] - pb[c * LEN + t];
        sdA[t * APAD + c] = d;
        int dd = c % 5, g = c / 5;                     // c = dd + 5g
        sdP[t * DCH + dd * 2 + g] = d;
    }
    __syncthreads();

    // helper decode (tid < 200): local abc = tid
    const int ha = tid / 100;          // a_local (0/1)
    const int hb = (tid / 10) % 10;    // b
    const int hc = tid % 10;           // c
    float s1 = 0.f, s2 = 0.f, s3 = 0.f;   // register-resident S1[a], S2[ab], S3[abc]

    // main decode (tid < 1000)
    const bool is_main = tid < 1000;
    const int abc_l = tid / 5;
    const int dd    = tid % 5;

    ull s4p = 0ull;      // (S4[abc,dd], S4[abc,dd+5])
    ull s5[10];          // [g*5+p]: e-pair p of d-group g
#pragma unroll
    for (int i = 0; i < 10; ++i) s5[i] = 0ull;

    for (int t = 0; t < NSEG; ++t) {
        if (tid < 200) {
            const float* dl = &sdA[t * APAD];
            float da = dl[2 * j + ha], db = dl[hb], dc = dl[hc];
            float P1 = fmaf(da, 1.f / 120.f, s1 * (1.f / 24.f));
            float P2 = fmaf(db, P1, s2 * (1.f / 6.f));
            float P3 = fmaf(dc, P2, s3 * 0.5f);
            float Q1 = fmaf(da, 1.f / 24.f, s1 * (1.f / 6.f));
            float Q2 = fmaf(db, Q1, s2 * 0.5f);
            float Y3 = fmaf(dc, Q2, s3);
            Hsh[t & 1][tid] = make_float2(P3, Y3);
            float Z1 = fmaf(da, 1.f / 6.f, s1 * 0.5f);
            float Z2 = fmaf(db, Z1, s2);
            s3 = fmaf(dc, Z2, s3);
            float W1 = fmaf(da, 0.5f, s1);
            s2 = fmaf(db, W1, s2);
            s1 += da;
        }
        __syncthreads();
        if (is_main) {
            const float* dl = &sdA[t * APAD];
            ulonglong2 e03 = *(const ulonglong2*)dl;                 // (δ0,δ1)(δ2,δ3)
            ulonglong2 e47 = *(const ulonglong2*)(dl + 4);           // (δ4,δ5)(δ6,δ7)
            ull e89        = *(const ull*)(dl + 8);                  // (δ8,δ9)
            ull dpp        = *(const ull*)&sdP[t * DCH + dd * 2];    // (δ_dd, δ_dd+5)
            float2 Hv = Hsh[t & 1][abc_l];
            ull Hxx = pk(Hv.x, Hv.x), Hyy = pk(Hv.y, Hv.y);
            ull X4p = ffma2(dpp, Hxx, s4p);                          // (X4_d0, X4_d1)
            s4p     = ffma2(dpp, Hyy, s4p);
            float x0, x1;
            upk(X4p, x0, x1);
            ull X00 = pk(x0, x0), X11 = pk(x1, x1);
            s5[0] = ffma2(X00, e03.x, s5[0]);
            s5[1] = ffma2(X00, e03.y, s5[1]);
            s5[2] = ffma2(X00, e47.x, s5[2]);
            s5[3] = ffma2(X00, e47.y, s5[3]);
            s5[4] = ffma2(X00, e89,   s5[4]);
            s5[5] = ffma2(X11, e03.x, s5[5]);
            s5[6] = ffma2(X11, e03.y, s5[6]);
            s5[7] = ffma2(X11, e47.x, s5[7]);
            s5[8] = ffma2(X11, e47.y, s5[8]);
            s5[9] = ffma2(X11, e89,   s5[9]);
        }
    }

    // ---- epilogue ----
    float* orow = out + (size_t)b * ROW;
    if (tid < 200) {
        if (hb == 0 && hc == 0) orow[2 * j + ha] = s1;
        if (hc == 0)            orow[10 + (2 * j + ha) * 10 + hb] = s2;
        orow[110 + 200 * j + tid] = s3;
    }
    if (is_main) {
        int abc   = 200 * j + abc_l;
        int abcd0 = abc * 10 + dd;
        int abcd1 = abc * 10 + dd + 5;
        float s40, s41;
        upk(s4p, s40, s41);
        orow[1110 + abcd0] = s40;
        orow[1110 + abcd1] = s41;
        ull* o5 = (ull*)(orow + 11110);   // 8B-aligned (11110*4 % 8 == 0, rows even)
#pragma unroll
        for (int p = 0; p < 5; ++p) {
            o5[abcd0 * 5 + p] = s5[p];
            o5[abcd1 * 5 + p] = s5[5 + p];
        }
    }
}

extern "C" void kernel_launch(void* const* d_in, const int* in_sizes, int n_in,
                              void* d_out, int out_size) {
    const float* path = (const float*)d_in[0];  // (256, 10, 128) fp32
    float* out = (float*)d_out;                 // (256, 111110) fp32
    sig_kernel<<<NB * CTAS_PER_B, THREADS>>>(path, out);
}

// round 3
// speedup vs baseline: 2.2132x; 1.7716x over previous
#include <cuda_runtime.h>

// Depth-5 path signature, B=256, d=10, L=128 (127 segments).
// Output row: [S1(10) | S2(100) | S3(1000) | S4(10000) | S5(100000)] = 111110 floats.
//
// Chen recurrence with rank-1 segment tensors (increment δ):
//   P3[abc] = S3/2 + δc*(S2/6 + δb*(S1/24 + δa/120))
//   Y3[abc] = S3   + δc*(S2/2 + δb*(S1/6  + δa/24))
//   X4[abcd] = S4[abcd] + δd*P3[abc];  S4 += Y3 ⊗ δ;  S5 += X4 ⊗ δ
//   S3 += δc*(S2 + δb*(S1/2 + δa/6));  S2 += δb*(S1 + δa/2);  S1 += δ
//
// CTA = (batch b, channel a). 200 threads: thread = (abc local bc, half of d).
// Thread owns 5 interleaved d-columns (d = 2*d_i + half): 5 S4 scalars + 25 packed
// S5 f32x2 accumulators in registers. Each thread redundantly maintains S1/S2/S3
// for its (a,b,c) in registers -> NO barriers, NO shared state in the main loop.

#define NB 256
#define DCH 10
#define LEN 128
#define NSEG 127
#define THREADS 200
#define ROW 111110
#define APAD 12   // padded sdA row stride: 48B rows, 16B-aligned

typedef unsigned long long ull;

__device__ __forceinline__ ull pk(float lo, float hi) {
    ull r;
    asm("mov.b64 %0, {%1, %2};" : "=l"(r) : "f"(lo), "f"(hi));
    return r;
}
__device__ __forceinline__ void upk(ull v, float& lo, float& hi) {
    asm("mov.b64 {%0, %1}, %2;" : "=f"(lo), "=f"(hi) : "l"(v));
}
__device__ __forceinline__ ull ffma2(ull a, ull b, ull c) {
    ull d;
    asm("fma.rn.f32x2 %0, %1, %2, %3;" : "=l"(d) : "l"(a), "l"(b), "l"(c));
    return d;
}

__global__ __launch_bounds__(THREADS, 3)
void sig_kernel(const float* __restrict__ path, float* __restrict__ out) {
    __shared__ __align__(16) float sdA[NSEG * APAD];   // [t][c]

    const int tid = threadIdx.x;
    const int b   = blockIdx.x / DCH;
    const int a   = blockIdx.x % DCH;

    // ---- segment increments (coalesced over t) ----
    const float* pb = path + b * (DCH * LEN);
    for (int idx = tid; idx < NSEG * DCH; idx += THREADS) {
        int c = idx / NSEG, t = idx % NSEG;
        sdA[t * APAD + c] = pb[c * LEN + t + 1] - pb[c * LEN + t];
    }
    __syncthreads();

    const int half  = tid / 100;        // d-halfset: d = 2*d_i + half
    const int bc    = tid % 100;        // local (b,c)
    const int hb    = bc / 10;
    const int hc    = bc % 10;

    float s1 = 0.f, s2 = 0.f, s3 = 0.f;   // private S1[a], S2[ab], S3[abc]
    float s4[5];                           // S4[abc, 2*d_i+half]
    ull   s5[5][5];                        // [d_i][e-pair p]
#pragma unroll
    for (int i = 0; i < 5; ++i) {
        s4[i] = 0.f;
#pragma unroll
        for (int p = 0; p < 5; ++p) s5[i][p] = 0ull;
    }

    const float* dl = sdA;
    for (int t = 0; t < NSEG; ++t, dl += APAD) {
        float4 v0 = *(const float4*)dl;         // δ0..δ3 (broadcast)
        float4 v1 = *(const float4*)(dl + 4);   // δ4..δ7
        float2 v2 = *(const float2*)(dl + 8);   // δ8, δ9
        float da = dl[a], db = dl[hb], dc = dl[hc];

        // Horner chains (imm-multiplier FFMA path, rt=1)
        float P1 = fmaf(da, 1.f / 120.f, s1 * (1.f / 24.f));
        float P2 = fmaf(db, P1, s2 * (1.f / 6.f));
        float P3 = fmaf(dc, P2, s3 * 0.5f);
        float Q1 = fmaf(da, 1.f / 24.f, s1 * (1.f / 6.f));
        float Q2 = fmaf(db, Q1, s2 * 0.5f);
        float Y3 = fmaf(dc, Q2, s3);
        // private state updates
        float Z1 = fmaf(da, 1.f / 6.f, s1 * 0.5f);
        float Z2 = fmaf(db, Z1, s2);
        s3 = fmaf(dc, Z2, s3);
        float W1 = fmaf(da, 0.5f, s1);
        s2 = fmaf(db, W1, s2);
        s1 += da;

        // e-pairs (adjacent channels), register pairs from the vector loads
        ull ep[5];
        ep[0] = pk(v0.x, v0.y);
        ep[1] = pk(v0.z, v0.w);
        ep[2] = pk(v1.x, v1.y);
        ep[3] = pk(v1.z, v1.w);
        ep[4] = pk(v2.x, v2.y);

        // this thread's 5 d-values (interleaved split, SELs not branches)
        float dloc[5];
        dloc[0] = half ? v0.y : v0.x;
        dloc[1] = half ? v0.w : v0.z;
        dloc[2] = half ? v1.y : v1.x;
        dloc[3] = half ? v1.w : v1.z;
        dloc[4] = half ? v2.y : v2.x;

#pragma unroll
        for (int i = 0; i < 5; ++i) {
            float X = fmaf(dloc[i], P3, s4[i]);     // X4[abc,d]
            s4[i]   = fmaf(dloc[i], Y3, s4[i]);     // S4 += Y3*δd
            ull X2  = pk(X, X);
#pragma unroll
            for (int p = 0; p < 5; ++p)
                s5[i][p] = ffma2(X2, ep[p], s5[i][p]);   // S5[abc,d,·] += X4*δe
        }
    }

    // ---- epilogue ----
    float* orow = out + (size_t)b * ROW;
    const int abc = a * 100 + bc;
    if (half == 0) {
        if (bc == 0) orow[a] = s1;
        if (hc == 0) orow[10 + a * 10 + hb] = s2;
        orow[110 + abc] = s3;
    }
    ull* o5 = (ull*)(orow + 11110);   // 8B-aligned: 11110*4 % 8 == 0
#pragma unroll
    for (int i = 0; i < 5; ++i) {
        int abcd = abc * 10 + 2 * i + half;
        orow[1110 + abcd] = s4[i];
#pragma unroll
        for (int p = 0; p < 5; ++p) o5[abcd * 5 + p] = s5[i][p];
    }
}

extern "C" void kernel_launch(void* const* d_in, const int* in_sizes, int n_in,
                              void* d_out, int out_size) {
    const float* path = (const float*)d_in[0];  // (256, 10, 128) fp32
    float* out = (float*)d_out;                 // (256, 111110) fp32
    sig_kernel<<<NB * DCH, THREADS>>>(path, out);
}